// round 10
// baseline (speedup 1.0000x reference)
#include <cuda_runtime.h>
#include <cuda_bf16.h>
#include <cstdint>
#include <math.h>

// ============================================================================
// StandardAttention, B=4, S=2048, D=2048, H=16, Dh=128, fp32.
// R10: resubmit of R9 (infra failure, never ran). GEMM at 16 warps / 512
//      threads per CTA (4 warps/SMSP) to hide LDS+HMMA latency; tile 128x256,
//      warp tile 64x32, pre-split bf16x2 hi/lo planes.
// Attention: SIMT flash kernel (unchanged from R7).
// ============================================================================

#define D_MODEL 2048
#define SEQ     2048
#define BATCH   4
#define NHEADS  16
#define DHEAD   128
#define MROWS   (BATCH * SEQ)          // 8192

__device__ float    g_Q  [ (size_t)MROWS * D_MODEL ];
__device__ float    g_K  [ (size_t)MROWS * D_MODEL ];
__device__ float    g_V  [ (size_t)MROWS * D_MODEL ];
__device__ float    g_AO [ (size_t)MROWS * D_MODEL ];
__device__ uint32_t g_Xhi[ (size_t)MROWS * D_MODEL / 2 ];
__device__ uint32_t g_Xlo[ (size_t)MROWS * D_MODEL / 2 ];
__device__ uint32_t g_Whi[ (size_t)D_MODEL * D_MODEL / 2 ];
__device__ uint32_t g_Wlo[ (size_t)D_MODEL * D_MODEL / 2 ];

// ---------------------------------------------------------------------------
// Helpers
// ---------------------------------------------------------------------------
__device__ __forceinline__ uint32_t smem_u32(const void* p) {
    uint32_t a;
    asm("{ .reg .u64 t; cvta.to.shared.u64 t, %1; cvt.u32.u64 %0, t; }"
        : "=r"(a) : "l"(p));
    return a;
}
__device__ __forceinline__ void cp_async16(uint32_t dst, const void* src) {
    asm volatile("cp.async.cg.shared.global [%0], [%1], 16;"
                 :: "r"(dst), "l"(src) : "memory");
}
__device__ __forceinline__ void cp_commit() {
    asm volatile("cp.async.commit_group;" ::: "memory");
}
template<int N> __device__ __forceinline__ void cp_wait() {
    asm volatile("cp.async.wait_group %0;" :: "n"(N) : "memory");
}

__device__ __forceinline__ void mma_bf16(float* d, const uint32_t* a,
                                         const uint32_t* b) {
    asm volatile(
        "mma.sync.aligned.m16n8k16.row.col.f32.bf16.bf16.f32 "
        "{%0,%1,%2,%3}, {%4,%5,%6,%7}, {%8,%9}, {%0,%1,%2,%3};"
        : "+f"(d[0]), "+f"(d[1]), "+f"(d[2]), "+f"(d[3])
        : "r"(a[0]), "r"(a[1]), "r"(a[2]), "r"(a[3]), "r"(b[0]), "r"(b[1]));
}

__device__ __forceinline__ void split2(float2 v, uint32_t& hi, uint32_t& lo) {
    asm("cvt.rn.bf16x2.f32 %0, %1, %2;" : "=r"(hi) : "f"(v.y), "f"(v.x));
    const float hx = __uint_as_float(hi << 16);
    const float hy = __uint_as_float(hi & 0xffff0000u);
    const float lx = v.x - hx;
    const float ly = v.y - hy;
    asm("cvt.rn.bf16x2.f32 %0, %1, %2;" : "=r"(lo) : "f"(ly), "f"(lx));
}

// ---------------------------------------------------------------------------
// Pre-split kernel: fp32 -> packed bf16x2 hi/lo planes.
// ---------------------------------------------------------------------------
__global__ void __launch_bounds__(256) split_kernel(
    const float* __restrict__ src, uint32_t* __restrict__ hi,
    uint32_t* __restrict__ lo, int n2)
{
    const int i = blockIdx.x * 256 + threadIdx.x;
    if (i < n2) {
        const float2 v = ((const float2*)src)[i];
        uint32_t h, l;
        split2(v, h, l);
        hi[i] = h;
        lo[i] = l;
    }
}

// ---------------------------------------------------------------------------
// Pre-split bf16x3 GEMM-NT, 512 threads (16 warps), CTA tile 128x256,
// warp tile 64x32 (wm = w>>3: 2 rows of warps; wn = w&7: 8 cols).
// BK=32, 3-stage cp.async. Plane row stride 20 u32: LDS.32 conflict-free.
// ---------------------------------------------------------------------------
#define GBM 128
#define GBN 256
#define GBK 32
#define GSTAGES 3
#define GTHREADS 512
#define NCHUNK (D_MODEL / GBK)          // 64
#define KW   (D_MODEL / 2)              // 1024 u32 per gmem row
#define PSTR 20
#define A_PL (GBM * PSTR)               // 2560
#define B_PL (GBN * PSTR)               // 5120
#define STAGE_U (2 * A_PL + 2 * B_PL)   // 15360
#define GEMM_SMEM_BYTES (GSTAGES * STAGE_U * 4)   // 184320

__global__ void __launch_bounds__(GTHREADS, 1) gemm_pre(
    const uint32_t* __restrict__ Ahi, const uint32_t* __restrict__ Alo,
    const uint32_t* __restrict__ Bhi, const uint32_t* __restrict__ Blo,
    float* __restrict__ C)
{
    extern __shared__ uint32_t smu[];
    const int t  = threadIdx.x;
    const int w  = t >> 5;
    const int l  = t & 31;
    const int g  = l >> 2;
    const int q  = l & 3;
    const int wm = w >> 3;      // 0..1, 64 rows each
    const int wn = w & 7;       // 0..7, 32 cols each
    const int bm = blockIdx.y * GBM;
    const int bn = blockIdx.x * GBN;

    float acc[4][4][4];
#pragma unroll
    for (int mi = 0; mi < 4; mi++)
#pragma unroll
        for (int ni = 0; ni < 4; ni++)
#pragma unroll
            for (int c = 0; c < 4; c++) acc[mi][ni][c] = 0.0f;

    auto load_stage = [&](int s, int chunk) {
        uint32_t* sAh = smu + s * STAGE_U;
        uint32_t* sAl = sAh + A_PL;
        uint32_t* sBh = sAl + A_PL;
        uint32_t* sBl = sBh + B_PL;
        const int col0 = chunk * 16;
        {   // A: 128 rows x 16 u32: one cp per plane per thread
            const int r = t >> 2, c = t & 3;
            const size_t go = (size_t)(bm + r) * KW + col0 + c * 4;
            cp_async16(smem_u32(sAh + r * PSTR + c * 4), Ahi + go);
            cp_async16(smem_u32(sAl + r * PSTR + c * 4), Alo + go);
        }
#pragma unroll
        for (int i = 0; i < 2; i++) {   // B: 256 rows
            const int idx = i * GTHREADS + t, r = idx >> 2, c = idx & 3;
            const size_t go = (size_t)(bn + r) * KW + col0 + c * 4;
            cp_async16(smem_u32(sBh + r * PSTR + c * 4), Bhi + go);
            cp_async16(smem_u32(sBl + r * PSTR + c * 4), Blo + go);
        }
    };

#pragma unroll
    for (int s = 0; s < GSTAGES - 1; s++) { load_stage(s, s); cp_commit(); }

    for (int c = 0; c < NCHUNK; c++) {
        __syncthreads();
        const int lc = c + GSTAGES - 1;
        if (lc < NCHUNK) load_stage(lc % GSTAGES, lc);
        cp_commit();
        cp_wait<GSTAGES - 2>();
        __syncthreads();

        const uint32_t* sAh = smu + (c % GSTAGES) * STAGE_U + (wm * 64) * PSTR;
        const uint32_t* sAl = sAh + A_PL;
        const uint32_t* sBh = smu + (c % GSTAGES) * STAGE_U + 2 * A_PL + (wn * 32) * PSTR;
        const uint32_t* sBl = sBh + B_PL;

#pragma unroll
        for (int ks = 0; ks < 2; ks++) {
            const int kb = ks * 8 + q;

            uint32_t bhi[4][2], blo[4][2];
#pragma unroll
            for (int ni = 0; ni < 4; ni++) {
                const int nrow = (ni * 8 + g) * PSTR;
                bhi[ni][0] = sBh[nrow + kb];
                bhi[ni][1] = sBh[nrow + kb + 4];
                blo[ni][0] = sBl[nrow + kb];
                blo[ni][1] = sBl[nrow + kb + 4];
            }

#pragma unroll
            for (int mi = 0; mi < 4; mi++) {
                const int r0 = (mi * 16 + g) * PSTR;
                const int r1 = r0 + 8 * PSTR;
                uint32_t ahi[4], alo[4];
                ahi[0] = sAh[r0 + kb];     ahi[1] = sAh[r1 + kb];
                ahi[2] = sAh[r0 + kb + 4]; ahi[3] = sAh[r1 + kb + 4];
                alo[0] = sAl[r0 + kb];     alo[1] = sAl[r1 + kb];
                alo[2] = sAl[r0 + kb + 4]; alo[3] = sAl[r1 + kb + 4];
#pragma unroll
                for (int ni = 0; ni < 4; ni++) mma_bf16(acc[mi][ni], ahi, bhi[ni]);
#pragma unroll
                for (int ni = 0; ni < 4; ni++) mma_bf16(acc[mi][ni], alo, bhi[ni]);
#pragma unroll
                for (int ni = 0; ni < 4; ni++) mma_bf16(acc[mi][ni], ahi, blo[ni]);
            }
        }
    }

#pragma unroll
    for (int mi = 0; mi < 4; mi++) {
        const int r0 = bm + wm * 64 + mi * 16 + g;
#pragma unroll
        for (int ni = 0; ni < 4; ni++) {
            const int col = bn + wn * 32 + ni * 8 + q * 2;
            *(float2*)&C[(size_t)r0 * D_MODEL + col] =
                make_float2(acc[mi][ni][0], acc[mi][ni][1]);
            *(float2*)&C[(size_t)(r0 + 8) * D_MODEL + col] =
                make_float2(acc[mi][ni][2], acc[mi][ni][3]);
        }
    }
}

// ---------------------------------------------------------------------------
// Flash attention (causal), SIMT — unchanged from R7 (2 CTAs/SM).
// ---------------------------------------------------------------------------
#define QS_STRIDE 128
#define KS_STRIDE 128
#define VS_STRIDE 128
#define PS_STRIDE 65
#define SM_QS 0
#define SM_KS (SM_QS + 64 * QS_STRIDE)
#define SM_VS (SM_KS + 64 * KS_STRIDE)
#define SM_PS (SM_VS + 64 * VS_STRIDE)
#define ATT_SMEM_FLOATS (SM_PS + 64 * PS_STRIDE)
#define ATT_SMEM_BYTES  (ATT_SMEM_FLOATS * 4)      // 114944
#define NEG_BIG (-1.0e30f)

__global__ void __launch_bounds__(256, 2) attn_kernel(
    const float* __restrict__ Q, const float* __restrict__ K,
    const float* __restrict__ V, float* __restrict__ O)
{
    extern __shared__ float sm[];
    float* Qs = sm + SM_QS;
    float* Ks = sm + SM_KS;
    float* Vs = sm + SM_VS;
    float* Ps = sm + SM_PS;

    const int t  = threadIdx.x;
    const int w  = t >> 5;
    const int l  = t & 31;
    const int bh = blockIdx.y;
    const int b  = bh >> 4;
    const int h  = bh & 15;
    const int mt = blockIdx.x;
    const size_t base = ((size_t)b * SEQ) * D_MODEL + (size_t)h * DHEAD;
    const float scale = 0.088388347648318447f;

#pragma unroll
    for (int it = 0; it < 8; it++) {
        const int i  = it * 256 + t;
        const int r  = i >> 5;
        const int c4 = (i & 31);
        *(float4*)&Qs[r * QS_STRIDE + c4 * 4] =
            *(const float4*)(Q + base + (size_t)(mt * 64 + r) * D_MODEL + c4 * 4);
    }

    float m_i[8], l_i[8], acc[8][4];
#pragma unroll
    for (int i = 0; i < 8; i++) {
        m_i[i] = NEG_BIG; l_i[i] = 0.0f;
        acc[i][0] = acc[i][1] = acc[i][2] = acc[i][3] = 0.0f;
    }

    const int r0 = w * 8;

    for (int nt = 0; nt <= mt; nt++) {
        __syncthreads();
#pragma unroll
        for (int it = 0; it < 8; it++) {
            const int i  = it * 256 + t;
            const int r  = i >> 5;
            const int c4 = (i & 31);
            const size_t goff = base + (size_t)(nt * 64 + r) * D_MODEL + c4 * 4;
            *(float4*)&Ks[r * KS_STRIDE + ((c4 ^ (r & 31)) * 4)] =
                *(const float4*)(K + goff);
            *(float4*)&Vs[r * VS_STRIDE + c4 * 4] = *(const float4*)(V + goff);
        }
        __syncthreads();

        float s0[8], s1[8];
#pragma unroll
        for (int i = 0; i < 8; i++) { s0[i] = 0.0f; s1[i] = 0.0f; }
#pragma unroll 4
        for (int k4 = 0; k4 < 32; k4++) {
            const int sc = (k4 ^ l) * 4;
            const float4 kv0 = *(const float4*)&Ks[l * KS_STRIDE + sc];
            const float4 kv1 = *(const float4*)&Ks[(32 + l) * KS_STRIDE + sc];
            const int kk = k4 * 4;
#pragma unroll
            for (int i = 0; i < 8; i++) {
                const float4 qv = *(const float4*)&Qs[(r0 + i) * QS_STRIDE + kk];
                s0[i] += qv.x * kv0.x + qv.y * kv0.y + qv.z * kv0.z + qv.w * kv0.w;
                s1[i] += qv.x * kv1.x + qv.y * kv1.y + qv.z * kv1.z + qv.w * kv1.w;
            }
        }

        const bool diag = (nt == mt);
#pragma unroll
        for (int i = 0; i < 8; i++) {
            const int qg = mt * 64 + r0 + i;
            float sv0 = s0[i] * scale;
            float sv1 = s1[i] * scale;
            if (diag) {
                if (nt * 64 + l      > qg) sv0 = NEG_BIG;
                if (nt * 64 + 32 + l > qg) sv1 = NEG_BIG;
            }
            float mx = fmaxf(sv0, sv1);
#pragma unroll
            for (int off = 16; off > 0; off >>= 1)
                mx = fmaxf(mx, __shfl_xor_sync(0xffffffffu, mx, off));
            const float mnew  = fmaxf(m_i[i], mx);
            const float alpha = __expf(m_i[i] - mnew);
            const float p0 = __expf(sv0 - mnew);
            const float p1 = __expf(sv1 - mnew);
            float rs = p0 + p1;
#pragma unroll
            for (int off = 16; off > 0; off >>= 1)
                rs += __shfl_xor_sync(0xffffffffu, rs, off);
            l_i[i] = l_i[i] * alpha + rs;
            m_i[i] = mnew;
            acc[i][0] *= alpha; acc[i][1] *= alpha;
            acc[i][2] *= alpha; acc[i][3] *= alpha;
            Ps[(r0 + i) * PS_STRIDE + l]      = p0;
            Ps[(r0 + i) * PS_STRIDE + 32 + l] = p1;
        }
        __syncwarp();

#pragma unroll 4
        for (int c = 0; c < 64; c++) {
            const float4 vv = *(const float4*)&Vs[c * VS_STRIDE + l * 4];
#pragma unroll
            for (int i = 0; i < 8; i++) {
                const float p = Ps[(r0 + i) * PS_STRIDE + c];
                acc[i][0] += p * vv.x;
                acc[i][1] += p * vv.y;
                acc[i][2] += p * vv.z;
                acc[i][3] += p * vv.w;
            }
        }
        __syncwarp();
    }

#pragma unroll
    for (int i = 0; i < 8; i++) {
        const float inv = 1.0f / l_i[i];
        const int qg = mt * 64 + r0 + i;
        float4 o = make_float4(acc[i][0] * inv, acc[i][1] * inv,
                               acc[i][2] * inv, acc[i][3] * inv);
        *(float4*)(O + base + (size_t)qg * D_MODEL + l * 4) = o;
    }
}

// ---------------------------------------------------------------------------
// Launcher
// ---------------------------------------------------------------------------
extern "C" void kernel_launch(void* const* d_in, const int* in_sizes, int n_in,
                              void* d_out, int out_size)
{
    const float* x  = (const float*)d_in[0];
    const float* Wq = (const float*)d_in[1];
    const float* Wk = (const float*)d_in[2];
    const float* Wv = (const float*)d_in[3];
    const float* Wo = (const float*)d_in[4];
    float* out = (float*)d_out;

    void *pQ, *pK, *pV, *pA, *pXh, *pXl, *pWh, *pWl;
    cudaGetSymbolAddress(&pQ,  g_Q);
    cudaGetSymbolAddress(&pK,  g_K);
    cudaGetSymbolAddress(&pV,  g_V);
    cudaGetSymbolAddress(&pA,  g_AO);
    cudaGetSymbolAddress(&pXh, g_Xhi);
    cudaGetSymbolAddress(&pXl, g_Xlo);
    cudaGetSymbolAddress(&pWh, g_Whi);
    cudaGetSymbolAddress(&pWl, g_Wlo);

    uint32_t* Xh = (uint32_t*)pXh; uint32_t* Xl = (uint32_t*)pXl;
    uint32_t* Wh = (uint32_t*)pWh; uint32_t* Wl = (uint32_t*)pWl;

    cudaFuncSetAttribute(gemm_pre,
                         cudaFuncAttributeMaxDynamicSharedMemorySize, GEMM_SMEM_BYTES);
    cudaFuncSetAttribute(attn_kernel,
                         cudaFuncAttributeMaxDynamicSharedMemorySize, ATT_SMEM_BYTES);

    const int n2x = MROWS * D_MODEL / 2;
    const int n2w = D_MODEL * D_MODEL / 2;
    const dim3 ggrid(D_MODEL / GBN, MROWS / GBM);        // (8, 64)
    const dim3 attn_grid(SEQ / 64, BATCH * NHEADS);      // (32, 64)

    split_kernel<<<n2x / 256, 256>>>(x, Xh, Xl, n2x);

    split_kernel<<<n2w / 256, 256>>>(Wq, Wh, Wl, n2w);
    gemm_pre<<<ggrid, GTHREADS, GEMM_SMEM_BYTES>>>(Xh, Xl, Wh, Wl, (float*)pQ);

    split_kernel<<<n2w / 256, 256>>>(Wk, Wh, Wl, n2w);
    gemm_pre<<<ggrid, GTHREADS, GEMM_SMEM_BYTES>>>(Xh, Xl, Wh, Wl, (float*)pK);

    split_kernel<<<n2w / 256, 256>>>(Wv, Wh, Wl, n2w);
    gemm_pre<<<ggrid, GTHREADS, GEMM_SMEM_BYTES>>>(Xh, Xl, Wh, Wl, (float*)pV);

    attn_kernel<<<attn_grid, 256, ATT_SMEM_BYTES>>>(
        (const float*)pQ, (const float*)pK, (const float*)pV, (float*)pA);

    split_kernel<<<n2x / 256, 256>>>((const float*)pA, Xh, Xl, n2x);
    split_kernel<<<n2w / 256, 256>>>(Wo, Wh, Wl, n2w);
    gemm_pre<<<ggrid, GTHREADS, GEMM_SMEM_BYTES>>>(Xh, Xl, Wh, Wl, out);
}

// round 11
// speedup vs baseline: 1.3982x; 1.3982x over previous
#include <cuda_runtime.h>
#include <cuda_bf16.h>
#include <cstdint>
#include <math.h>

// ============================================================================
// StandardAttention, B=4, S=2048, D=2048, H=16, Dh=128, fp32.
// R11: tensorized flash attention (mma.sync bf16x3 for QK^T and PV, online
//      softmax in fragment registers, P = S-frag reused as A-frag).
//      GEMMs unchanged (R8 gemm_pre, 256 thr) — they sit at the legacy
//      HMMA rt16 ceiling; attention was the non-ceiling-bound half.
// ============================================================================

#define D_MODEL 2048
#define SEQ     2048
#define BATCH   4
#define NHEADS  16
#define DHEAD   128
#define MROWS   (BATCH * SEQ)          // 8192

__device__ float    g_Q  [ (size_t)MROWS * D_MODEL ];
__device__ float    g_K  [ (size_t)MROWS * D_MODEL ];
__device__ float    g_V  [ (size_t)MROWS * D_MODEL ];
__device__ float    g_AO [ (size_t)MROWS * D_MODEL ];
__device__ uint32_t g_Xhi[ (size_t)MROWS * D_MODEL / 2 ];
__device__ uint32_t g_Xlo[ (size_t)MROWS * D_MODEL / 2 ];
__device__ uint32_t g_Whi[ (size_t)D_MODEL * D_MODEL / 2 ];
__device__ uint32_t g_Wlo[ (size_t)D_MODEL * D_MODEL / 2 ];
__device__ uint32_t g_QPh[ (size_t)MROWS * D_MODEL / 2 ];
__device__ uint32_t g_QPl[ (size_t)MROWS * D_MODEL / 2 ];
__device__ uint32_t g_KPh[ (size_t)MROWS * D_MODEL / 2 ];
__device__ uint32_t g_KPl[ (size_t)MROWS * D_MODEL / 2 ];

// ---------------------------------------------------------------------------
// Helpers
// ---------------------------------------------------------------------------
__device__ __forceinline__ uint32_t smem_u32(const void* p) {
    uint32_t a;
    asm("{ .reg .u64 t; cvta.to.shared.u64 t, %1; cvt.u32.u64 %0, t; }"
        : "=r"(a) : "l"(p));
    return a;
}
__device__ __forceinline__ void cp_async16(uint32_t dst, const void* src) {
    asm volatile("cp.async.cg.shared.global [%0], [%1], 16;"
                 :: "r"(dst), "l"(src) : "memory");
}
__device__ __forceinline__ void cp_commit() {
    asm volatile("cp.async.commit_group;" ::: "memory");
}
template<int N> __device__ __forceinline__ void cp_wait() {
    asm volatile("cp.async.wait_group %0;" :: "n"(N) : "memory");
}

__device__ __forceinline__ void mma_bf16(float* d, const uint32_t* a,
                                         const uint32_t* b) {
    asm volatile(
        "mma.sync.aligned.m16n8k16.row.col.f32.bf16.bf16.f32 "
        "{%0,%1,%2,%3}, {%4,%5,%6,%7}, {%8,%9}, {%0,%1,%2,%3};"
        : "+f"(d[0]), "+f"(d[1]), "+f"(d[2]), "+f"(d[3])
        : "r"(a[0]), "r"(a[1]), "r"(a[2]), "r"(a[3]), "r"(b[0]), "r"(b[1]));
}

// Split (x,y) into packed bf16x2 hi (low half = x) and lo residual.
__device__ __forceinline__ void split2(float2 v, uint32_t& hi, uint32_t& lo) {
    asm("cvt.rn.bf16x2.f32 %0, %1, %2;" : "=r"(hi) : "f"(v.y), "f"(v.x));
    const float hx = __uint_as_float(hi << 16);
    const float hy = __uint_as_float(hi & 0xffff0000u);
    const float lx = v.x - hx;
    const float ly = v.y - hy;
    asm("cvt.rn.bf16x2.f32 %0, %1, %2;" : "=r"(lo) : "f"(ly), "f"(lx));
}

// ---------------------------------------------------------------------------
// Pre-split kernel: fp32 -> packed bf16x2 hi/lo planes.
// ---------------------------------------------------------------------------
__global__ void __launch_bounds__(256) split_kernel(
    const float* __restrict__ src, uint32_t* __restrict__ hi,
    uint32_t* __restrict__ lo, int n2)
{
    const int i = blockIdx.x * 256 + threadIdx.x;
    if (i < n2) {
        const float2 v = ((const float2*)src)[i];
        uint32_t h, l;
        split2(v, h, l);
        hi[i] = h;
        lo[i] = l;
    }
}

// ---------------------------------------------------------------------------
// Pre-split bf16x3 GEMM-NT (R8 version, 256 threads, CTA 128x256, BK=32).
// ---------------------------------------------------------------------------
#define GBM 128
#define GBN 256
#define GBK 32
#define GSTAGES 3
#define NCHUNK (D_MODEL / GBK)          // 64
#define KW   (D_MODEL / 2)              // 1024 u32 per gmem row
#define PSTR 20
#define A_PL (GBM * PSTR)               // 2560
#define B_PL (GBN * PSTR)               // 5120
#define STAGE_U (2 * A_PL + 2 * B_PL)   // 15360
#define GEMM_SMEM_BYTES (GSTAGES * STAGE_U * 4)   // 184320

__global__ void __launch_bounds__(256, 1) gemm_pre(
    const uint32_t* __restrict__ Ahi, const uint32_t* __restrict__ Alo,
    const uint32_t* __restrict__ Bhi, const uint32_t* __restrict__ Blo,
    float* __restrict__ C)
{
    extern __shared__ uint32_t smu[];
    const int t  = threadIdx.x;
    const int w  = t >> 5;
    const int l  = t & 31;
    const int g  = l >> 2;
    const int q  = l & 3;
    const int wm = w >> 2;
    const int wn = w & 3;
    const int bm = blockIdx.y * GBM;
    const int bn = blockIdx.x * GBN;

    float acc[4][8][4];
#pragma unroll
    for (int mi = 0; mi < 4; mi++)
#pragma unroll
        for (int ni = 0; ni < 8; ni++)
#pragma unroll
            for (int c = 0; c < 4; c++) acc[mi][ni][c] = 0.0f;

    auto load_stage = [&](int s, int chunk) {
        uint32_t* sAh = smu + s * STAGE_U;
        uint32_t* sAl = sAh + A_PL;
        uint32_t* sBh = sAl + A_PL;
        uint32_t* sBl = sBh + B_PL;
        const int col0 = chunk * 16;
#pragma unroll
        for (int i = 0; i < 2; i++) {
            const int idx = i * 256 + t, r = idx >> 2, c = idx & 3;
            const size_t go = (size_t)(bm + r) * KW + col0 + c * 4;
            cp_async16(smem_u32(sAh + r * PSTR + c * 4), Ahi + go);
            cp_async16(smem_u32(sAl + r * PSTR + c * 4), Alo + go);
        }
#pragma unroll
        for (int i = 0; i < 4; i++) {
            const int idx = i * 256 + t, r = idx >> 2, c = idx & 3;
            const size_t go = (size_t)(bn + r) * KW + col0 + c * 4;
            cp_async16(smem_u32(sBh + r * PSTR + c * 4), Bhi + go);
            cp_async16(smem_u32(sBl + r * PSTR + c * 4), Blo + go);
        }
    };

#pragma unroll
    for (int s = 0; s < GSTAGES - 1; s++) { load_stage(s, s); cp_commit(); }

    for (int c = 0; c < NCHUNK; c++) {
        __syncthreads();
        const int lc = c + GSTAGES - 1;
        if (lc < NCHUNK) load_stage(lc % GSTAGES, lc);
        cp_commit();
        cp_wait<GSTAGES - 2>();
        __syncthreads();

        const uint32_t* sAh = smu + (c % GSTAGES) * STAGE_U + (wm * 64) * PSTR;
        const uint32_t* sAl = sAh + A_PL;
        const uint32_t* sBh = smu + (c % GSTAGES) * STAGE_U + 2 * A_PL + (wn * 64) * PSTR;
        const uint32_t* sBl = sBh + B_PL;

#pragma unroll
        for (int ks = 0; ks < 2; ks++) {
            const int kb = ks * 8 + q;

            uint32_t bhi[8][2], blo[8][2];
#pragma unroll
            for (int ni = 0; ni < 8; ni++) {
                const int nrow = (ni * 8 + g) * PSTR;
                bhi[ni][0] = sBh[nrow + kb];
                bhi[ni][1] = sBh[nrow + kb + 4];
                blo[ni][0] = sBl[nrow + kb];
                blo[ni][1] = sBl[nrow + kb + 4];
            }

#pragma unroll
            for (int mi = 0; mi < 4; mi++) {
                const int r0 = (mi * 16 + g) * PSTR;
                const int r1 = r0 + 8 * PSTR;
                uint32_t ahi[4], alo[4];
                ahi[0] = sAh[r0 + kb];     ahi[1] = sAh[r1 + kb];
                ahi[2] = sAh[r0 + kb + 4]; ahi[3] = sAh[r1 + kb + 4];
                alo[0] = sAl[r0 + kb];     alo[1] = sAl[r1 + kb];
                alo[2] = sAl[r0 + kb + 4]; alo[3] = sAl[r1 + kb + 4];
#pragma unroll
                for (int ni = 0; ni < 8; ni++) mma_bf16(acc[mi][ni], ahi, bhi[ni]);
#pragma unroll
                for (int ni = 0; ni < 8; ni++) mma_bf16(acc[mi][ni], alo, bhi[ni]);
#pragma unroll
                for (int ni = 0; ni < 8; ni++) mma_bf16(acc[mi][ni], ahi, blo[ni]);
            }
        }
    }

#pragma unroll
    for (int mi = 0; mi < 4; mi++) {
        const int r0 = bm + wm * 64 + mi * 16 + g;
#pragma unroll
        for (int ni = 0; ni < 8; ni++) {
            const int col = bn + wn * 64 + ni * 8 + q * 2;
            *(float2*)&C[(size_t)r0 * D_MODEL + col] =
                make_float2(acc[mi][ni][0], acc[mi][ni][1]);
            *(float2*)&C[(size_t)(r0 + 8) * D_MODEL + col] =
                make_float2(acc[mi][ni][2], acc[mi][ni][3]);
        }
    }
}

// ---------------------------------------------------------------------------
// Tensorized flash attention (causal), mma.sync bf16x3.
// CTA: 128 threads (4 warps), 64 q-rows of one (b,h); warp w owns rows
// 16w..16w+15. QK: Q(A-frag), K(B-frag) from hi/lo planes in smem.
// PV: P = S C-frag reused directly as A-frag (bf16 hi/lo in-reg split);
// V converted per-tile to kv-packed hi/lo smem planes.
// ---------------------------------------------------------------------------
#define AT_THREADS 128
#define QKSTR 68                        // u32 row stride for Q/K planes
#define VSTR  136                       // u32 row stride for V planes
#define SQH 0
#define SQL (SQH + 64 * QKSTR)          // 4352
#define SKH (SQL + 64 * QKSTR)          // 8704
#define SKL (SKH + 64 * QKSTR)          // 13056
#define SVH (SKL + 64 * QKSTR)          // 17408
#define SVL (SVH + 32 * VSTR)           // 21760
#define AT_SMEM_U (SVL + 32 * VSTR)     // 26112
#define AT_SMEM_BYTES (AT_SMEM_U * 4)   // 104448
#define NEG_BIG (-1.0e30f)

__global__ void __launch_bounds__(AT_THREADS, 2) attn_mma(
    const uint32_t* __restrict__ Qh, const uint32_t* __restrict__ Ql,
    const uint32_t* __restrict__ Kh, const uint32_t* __restrict__ Kl,
    const float* __restrict__ V, float* __restrict__ O)
{
    extern __shared__ uint32_t su[];
    uint32_t* qh_s = su + SQH;
    uint32_t* ql_s = su + SQL;
    uint32_t* kh_s = su + SKH;
    uint32_t* kl_s = su + SKL;
    uint32_t* vh_s = su + SVH;
    uint32_t* vl_s = su + SVL;

    const int t  = threadIdx.x;
    const int w  = t >> 5;
    const int l  = t & 31;
    const int g  = l >> 2;
    const int q  = l & 3;
    const int bh = blockIdx.y;
    const int b  = bh >> 4;
    const int h  = bh & 15;
    const int mt = gridDim.x - 1 - blockIdx.x;   // heavy tiles scheduled first
    const float scale = 0.088388347648318447f;   // 1/sqrt(128)

    // Load Q planes (64 x 64 u32 each) once.
    {
        const size_t prow0 = (size_t)b * SEQ + mt * 64;
        const int pcol = h * 64;
#pragma unroll
        for (int it = 0; it < 8; it++) {
            const int idx = it * AT_THREADS + t;
            const int r = idx >> 4;
            const int c4 = (idx & 15) * 4;
            *(uint4*)&qh_s[r * QKSTR + c4] =
                *(const uint4*)&Qh[(prow0 + r) * KW + pcol + c4];
            *(uint4*)&ql_s[r * QKSTR + c4] =
                *(const uint4*)&Ql[(prow0 + r) * KW + pcol + c4];
        }
    }

    float o[16][4];
#pragma unroll
    for (int n2 = 0; n2 < 16; n2++)
#pragma unroll
        for (int c = 0; c < 4; c++) o[n2][c] = 0.0f;
    float m_A = NEG_BIG, m_B = NEG_BIG, l_A = 0.0f, l_B = 0.0f;

    const int rowA = mt * 64 + 16 * w + g;       // global q row (lane rows A/B)
    const int rowB = rowA + 8;

    for (int nt = 0; nt <= mt; nt++) {
        __syncthreads();
        // Load K planes for this kv tile.
        {
            const size_t krow0 = (size_t)b * SEQ + nt * 64;
            const int pcol = h * 64;
#pragma unroll
            for (int it = 0; it < 8; it++) {
                const int idx = it * AT_THREADS + t;
                const int r = idx >> 4;
                const int c4 = (idx & 15) * 4;
                *(uint4*)&kh_s[r * QKSTR + c4] =
                    *(const uint4*)&Kh[(krow0 + r) * KW + pcol + c4];
                *(uint4*)&kl_s[r * QKSTR + c4] =
                    *(const uint4*)&Kl[(krow0 + r) * KW + pcol + c4];
            }
            // V convert: fp32 [64][128] -> kv-packed hi/lo planes [32][128].
            const size_t vbase = ((size_t)b * SEQ + nt * 64) * D_MODEL + h * DHEAD;
#pragma unroll 8
            for (int kp = 0; kp < 32; kp++) {
                const float v0 = V[vbase + (size_t)(2 * kp)     * D_MODEL + t];
                const float v1 = V[vbase + (size_t)(2 * kp + 1) * D_MODEL + t];
                uint32_t hi, lo;
                split2(make_float2(v0, v1), hi, lo);
                vh_s[kp * VSTR + t] = hi;
                vl_s[kp * VSTR + t] = lo;
            }
        }
        __syncthreads();

        // ---- S = Q K^T (bf16x3), fragment accumulate ----
        float s[8][4];
#pragma unroll
        for (int j = 0; j < 8; j++)
#pragma unroll
            for (int c = 0; c < 4; c++) s[j][c] = 0.0f;

        const int arow0 = (16 * w + g) * QKSTR;
        const int arow1 = arow0 + 8 * QKSTR;
#pragma unroll
        for (int c = 0; c < 8; c++) {
            const int kcol = 8 * c + q;
            uint32_t a_h[4], a_l[4];
            a_h[0] = qh_s[arow0 + kcol];     a_h[1] = qh_s[arow1 + kcol];
            a_h[2] = qh_s[arow0 + kcol + 4]; a_h[3] = qh_s[arow1 + kcol + 4];
            a_l[0] = ql_s[arow0 + kcol];     a_l[1] = ql_s[arow1 + kcol];
            a_l[2] = ql_s[arow0 + kcol + 4]; a_l[3] = ql_s[arow1 + kcol + 4];
#pragma unroll
            for (int j = 0; j < 8; j++) {
                const int brow = (8 * j + g) * QKSTR;
                uint32_t b_h[2] = { kh_s[brow + kcol], kh_s[brow + kcol + 4] };
                uint32_t b_l[2] = { kl_s[brow + kcol], kl_s[brow + kcol + 4] };
                mma_bf16(s[j], a_h, b_h);
                mma_bf16(s[j], a_l, b_h);
                mma_bf16(s[j], a_h, b_l);
            }
        }

        // ---- scale + causal mask ----
        const bool diag = (nt == mt);
#pragma unroll
        for (int j = 0; j < 8; j++) {
            s[j][0] *= scale; s[j][1] *= scale;
            s[j][2] *= scale; s[j][3] *= scale;
            if (diag) {
                const int col = nt * 64 + 8 * j + 2 * q;
                if (col     > rowA) s[j][0] = NEG_BIG;
                if (col + 1 > rowA) s[j][1] = NEG_BIG;
                if (col     > rowB) s[j][2] = NEG_BIG;
                if (col + 1 > rowB) s[j][3] = NEG_BIG;
            }
        }

        // ---- online softmax (rows A and B) ----
        float mxA = NEG_BIG, mxB = NEG_BIG;
#pragma unroll
        for (int j = 0; j < 8; j++) {
            mxA = fmaxf(mxA, fmaxf(s[j][0], s[j][1]));
            mxB = fmaxf(mxB, fmaxf(s[j][2], s[j][3]));
        }
        mxA = fmaxf(mxA, __shfl_xor_sync(0xffffffffu, mxA, 1));
        mxA = fmaxf(mxA, __shfl_xor_sync(0xffffffffu, mxA, 2));
        mxB = fmaxf(mxB, __shfl_xor_sync(0xffffffffu, mxB, 1));
        mxB = fmaxf(mxB, __shfl_xor_sync(0xffffffffu, mxB, 2));

        const float mAn = fmaxf(m_A, mxA);
        const float mBn = fmaxf(m_B, mxB);
        const float alA = __expf(m_A - mAn);
        const float alB = __expf(m_B - mBn);
        m_A = mAn; m_B = mBn;

        float smA = 0.0f, smB = 0.0f;
#pragma unroll
        for (int j = 0; j < 8; j++) {
            s[j][0] = __expf(s[j][0] - m_A);
            s[j][1] = __expf(s[j][1] - m_A);
            s[j][2] = __expf(s[j][2] - m_B);
            s[j][3] = __expf(s[j][3] - m_B);
            smA += s[j][0] + s[j][1];
            smB += s[j][2] + s[j][3];
        }
        smA += __shfl_xor_sync(0xffffffffu, smA, 1);
        smA += __shfl_xor_sync(0xffffffffu, smA, 2);
        smB += __shfl_xor_sync(0xffffffffu, smB, 1);
        smB += __shfl_xor_sync(0xffffffffu, smB, 2);
        l_A = l_A * alA + smA;
        l_B = l_B * alB + smB;

#pragma unroll
        for (int n2 = 0; n2 < 16; n2++) {
            o[n2][0] *= alA; o[n2][1] *= alA;
            o[n2][2] *= alB; o[n2][3] *= alB;
        }

        // ---- P fragments: S C-frag -> A-frag, split hi/lo ----
        uint32_t p_h[4][4], p_l[4][4];
#pragma unroll
        for (int c = 0; c < 4; c++) {
            split2(make_float2(s[2 * c][0],     s[2 * c][1]),     p_h[c][0], p_l[c][0]);
            split2(make_float2(s[2 * c][2],     s[2 * c][3]),     p_h[c][1], p_l[c][1]);
            split2(make_float2(s[2 * c + 1][0], s[2 * c + 1][1]), p_h[c][2], p_l[c][2]);
            split2(make_float2(s[2 * c + 1][2], s[2 * c + 1][3]), p_h[c][3], p_l[c][3]);
        }

        // ---- O += P V (bf16x3) ----
#pragma unroll
        for (int n2 = 0; n2 < 16; n2++) {
            const int vcol = 8 * n2 + g;
#pragma unroll
            for (int c = 0; c < 4; c++) {
                const int kp0 = 8 * c + q;
                uint32_t v_h[2] = { vh_s[kp0 * VSTR + vcol], vh_s[(kp0 + 4) * VSTR + vcol] };
                uint32_t v_l[2] = { vl_s[kp0 * VSTR + vcol], vl_s[(kp0 + 4) * VSTR + vcol] };
                mma_bf16(o[n2], p_h[c], v_h);
                mma_bf16(o[n2], p_l[c], v_h);
                mma_bf16(o[n2], p_h[c], v_l);
            }
        }
    }

    // ---- epilogue ----
    const float invA = 1.0f / l_A;
    const float invB = 1.0f / l_B;
    const size_t obase = (size_t)b * SEQ * D_MODEL + (size_t)h * DHEAD;
#pragma unroll
    for (int n2 = 0; n2 < 16; n2++) {
        const int col = 8 * n2 + 2 * q;
        *(float2*)&O[obase + (size_t)rowA * D_MODEL + col] =
            make_float2(o[n2][0] * invA, o[n2][1] * invA);
        *(float2*)&O[obase + (size_t)rowB * D_MODEL + col] =
            make_float2(o[n2][2] * invB, o[n2][3] * invB);
    }
}

// ---------------------------------------------------------------------------
// Launcher
// ---------------------------------------------------------------------------
extern "C" void kernel_launch(void* const* d_in, const int* in_sizes, int n_in,
                              void* d_out, int out_size)
{
    const float* x  = (const float*)d_in[0];
    const float* Wq = (const float*)d_in[1];
    const float* Wk = (const float*)d_in[2];
    const float* Wv = (const float*)d_in[3];
    const float* Wo = (const float*)d_in[4];
    float* out = (float*)d_out;

    void *pQ, *pK, *pV, *pA, *pXh, *pXl, *pWh, *pWl, *pQh, *pQl, *pKh, *pKl;
    cudaGetSymbolAddress(&pQ,  g_Q);
    cudaGetSymbolAddress(&pK,  g_K);
    cudaGetSymbolAddress(&pV,  g_V);
    cudaGetSymbolAddress(&pA,  g_AO);
    cudaGetSymbolAddress(&pXh, g_Xhi);
    cudaGetSymbolAddress(&pXl, g_Xlo);
    cudaGetSymbolAddress(&pWh, g_Whi);
    cudaGetSymbolAddress(&pWl, g_Wlo);
    cudaGetSymbolAddress(&pQh, g_QPh);
    cudaGetSymbolAddress(&pQl, g_QPl);
    cudaGetSymbolAddress(&pKh, g_KPh);
    cudaGetSymbolAddress(&pKl, g_KPl);

    uint32_t* Xh = (uint32_t*)pXh; uint32_t* Xl = (uint32_t*)pXl;
    uint32_t* Wh = (uint32_t*)pWh; uint32_t* Wl = (uint32_t*)pWl;

    cudaFuncSetAttribute(gemm_pre,
                         cudaFuncAttributeMaxDynamicSharedMemorySize, GEMM_SMEM_BYTES);
    cudaFuncSetAttribute(attn_mma,
                         cudaFuncAttributeMaxDynamicSharedMemorySize, AT_SMEM_BYTES);

    const int n2x = MROWS * D_MODEL / 2;
    const int n2w = D_MODEL * D_MODEL / 2;
    const dim3 ggrid(D_MODEL / GBN, MROWS / GBM);        // (8, 64)
    const dim3 attn_grid(SEQ / 64, BATCH * NHEADS);      // (32, 64)

    split_kernel<<<n2x / 256, 256>>>(x, Xh, Xl, n2x);

    split_kernel<<<n2w / 256, 256>>>(Wq, Wh, Wl, n2w);
    gemm_pre<<<ggrid, 256, GEMM_SMEM_BYTES>>>(Xh, Xl, Wh, Wl, (float*)pQ);

    split_kernel<<<n2w / 256, 256>>>(Wk, Wh, Wl, n2w);
    gemm_pre<<<ggrid, 256, GEMM_SMEM_BYTES>>>(Xh, Xl, Wh, Wl, (float*)pK);

    split_kernel<<<n2w / 256, 256>>>(Wv, Wh, Wl, n2w);
    gemm_pre<<<ggrid, 256, GEMM_SMEM_BYTES>>>(Xh, Xl, Wh, Wl, (float*)pV);

    // split Q and K to bf16x2 planes for tensorized attention
    split_kernel<<<n2x / 256, 256>>>((const float*)pQ,
                                     (uint32_t*)pQh, (uint32_t*)pQl, n2x);
    split_kernel<<<n2x / 256, 256>>>((const float*)pK,
                                     (uint32_t*)pKh, (uint32_t*)pKl, n2x);

    attn_mma<<<attn_grid, AT_THREADS, AT_SMEM_BYTES>>>(
        (const uint32_t*)pQh, (const uint32_t*)pQl,
        (const uint32_t*)pKh, (const uint32_t*)pKl,
        (const float*)pV, (float*)pA);

    split_kernel<<<n2x / 256, 256>>>((const float*)pA, Xh, Xl, n2x);
    split_kernel<<<n2w / 256, 256>>>(Wo, Wh, Wl, n2w);
    gemm_pre<<<ggrid, 256, GEMM_SMEM_BYTES>>>(Xh, Xl, Wh, Wl, out);
}

// round 13
// speedup vs baseline: 1.4971x; 1.0707x over previous
#include <cuda_runtime.h>
#include <cuda_bf16.h>
#include <cstdint>
#include <math.h>

// ============================================================================
// StandardAttention, B=4, S=2048, D=2048, H=16, Dh=128, fp32.
// R13: resubmit of R12 (infra failure, never ran).
//      (1) fused QKV projection GEMM over [Wq;Wk;Wv] (pays wave tail once),
//      (2) fused epilogue writes Q/K bf16x2 planes directly (V fp32),
//      (3) attention epilogue writes AO planes directly.
// ============================================================================

#define D_MODEL 2048
#define SEQ     2048
#define BATCH   4
#define NHEADS  16
#define DHEAD   128
#define MROWS   (BATCH * SEQ)          // 8192

__device__ float    g_V  [ (size_t)MROWS * D_MODEL ];
__device__ uint32_t g_Xhi[ (size_t)MROWS * D_MODEL / 2 ];   // x planes, then AO planes
__device__ uint32_t g_Xlo[ (size_t)MROWS * D_MODEL / 2 ];
__device__ uint32_t g_Whi[ (size_t)3 * D_MODEL * D_MODEL / 2 ]; // Wq|Wk|Wv (Wo reuses slice 0)
__device__ uint32_t g_Wlo[ (size_t)3 * D_MODEL * D_MODEL / 2 ];
__device__ uint32_t g_QPh[ (size_t)MROWS * D_MODEL / 2 ];
__device__ uint32_t g_QPl[ (size_t)MROWS * D_MODEL / 2 ];
__device__ uint32_t g_KPh[ (size_t)MROWS * D_MODEL / 2 ];
__device__ uint32_t g_KPl[ (size_t)MROWS * D_MODEL / 2 ];

// ---------------------------------------------------------------------------
// Helpers
// ---------------------------------------------------------------------------
__device__ __forceinline__ uint32_t smem_u32(const void* p) {
    uint32_t a;
    asm("{ .reg .u64 t; cvta.to.shared.u64 t, %1; cvt.u32.u64 %0, t; }"
        : "=r"(a) : "l"(p));
    return a;
}
__device__ __forceinline__ void cp_async16(uint32_t dst, const void* src) {
    asm volatile("cp.async.cg.shared.global [%0], [%1], 16;"
                 :: "r"(dst), "l"(src) : "memory");
}
__device__ __forceinline__ void cp_commit() {
    asm volatile("cp.async.commit_group;" ::: "memory");
}
template<int N> __device__ __forceinline__ void cp_wait() {
    asm volatile("cp.async.wait_group %0;" :: "n"(N) : "memory");
}

__device__ __forceinline__ void mma_bf16(float* d, const uint32_t* a,
                                         const uint32_t* b) {
    asm volatile(
        "mma.sync.aligned.m16n8k16.row.col.f32.bf16.bf16.f32 "
        "{%0,%1,%2,%3}, {%4,%5,%6,%7}, {%8,%9}, {%0,%1,%2,%3};"
        : "+f"(d[0]), "+f"(d[1]), "+f"(d[2]), "+f"(d[3])
        : "r"(a[0]), "r"(a[1]), "r"(a[2]), "r"(a[3]), "r"(b[0]), "r"(b[1]));
}

__device__ __forceinline__ void split2(float2 v, uint32_t& hi, uint32_t& lo) {
    asm("cvt.rn.bf16x2.f32 %0, %1, %2;" : "=r"(hi) : "f"(v.y), "f"(v.x));
    const float hx = __uint_as_float(hi << 16);
    const float hy = __uint_as_float(hi & 0xffff0000u);
    const float lx = v.x - hx;
    const float ly = v.y - hy;
    asm("cvt.rn.bf16x2.f32 %0, %1, %2;" : "=r"(lo) : "f"(ly), "f"(lx));
}

// ---------------------------------------------------------------------------
// Pre-split kernel: fp32 -> packed bf16x2 hi/lo planes.
// ---------------------------------------------------------------------------
__global__ void __launch_bounds__(256) split_kernel(
    const float* __restrict__ src, uint32_t* __restrict__ hi,
    uint32_t* __restrict__ lo, int n2)
{
    const int i = blockIdx.x * 256 + threadIdx.x;
    if (i < n2) {
        const float2 v = ((const float2*)src)[i];
        uint32_t h, l;
        split2(v, h, l);
        hi[i] = h;
        lo[i] = l;
    }
}

// ---------------------------------------------------------------------------
// GEMM common: 256 threads, CTA 128x256, BK=32, 3-stage cp.async,
// warp tile 64x64, pre-split bf16x2 hi/lo planes (PSTR=20, conflict-free).
// ---------------------------------------------------------------------------
#define GBM 128
#define GBN 256
#define GBK 32
#define GSTAGES 3
#define NCHUNK (D_MODEL / GBK)          // 64
#define KW   (D_MODEL / 2)              // 1024 u32 per plane row
#define PSTR 20
#define A_PL (GBM * PSTR)               // 2560
#define B_PL (GBN * PSTR)               // 5120
#define STAGE_U (2 * A_PL + 2 * B_PL)   // 15360
#define GEMM_SMEM_BYTES (GSTAGES * STAGE_U * 4)   // 184320

// Mainloop macro body shared by both GEMM kernels (defines acc).
#define GEMM_MAINLOOP(Ahi, Alo, Bhi, Blo)                                      \
    float acc[4][8][4];                                                        \
    _Pragma("unroll")                                                          \
    for (int mi = 0; mi < 4; mi++)                                             \
        _Pragma("unroll")                                                      \
        for (int ni = 0; ni < 8; ni++)                                         \
            _Pragma("unroll")                                                  \
            for (int cc = 0; cc < 4; cc++) acc[mi][ni][cc] = 0.0f;             \
    auto load_stage = [&](int s, int chunk) {                                  \
        uint32_t* sAh = smu + s * STAGE_U;                                     \
        uint32_t* sAl = sAh + A_PL;                                            \
        uint32_t* sBh = sAl + A_PL;                                            \
        uint32_t* sBl = sBh + B_PL;                                            \
        const int col0 = chunk * 16;                                           \
        _Pragma("unroll")                                                      \
        for (int i = 0; i < 2; i++) {                                          \
            const int idx = i * 256 + t, r = idx >> 2, c = idx & 3;            \
            const size_t go = (size_t)(bm + r) * KW + col0 + c * 4;            \
            cp_async16(smem_u32(sAh + r * PSTR + c * 4), Ahi + go);            \
            cp_async16(smem_u32(sAl + r * PSTR + c * 4), Alo + go);            \
        }                                                                      \
        _Pragma("unroll")                                                      \
        for (int i = 0; i < 4; i++) {                                          \
            const int idx = i * 256 + t, r = idx >> 2, c = idx & 3;            \
            const size_t go = (size_t)(bn + r) * KW + col0 + c * 4;            \
            cp_async16(smem_u32(sBh + r * PSTR + c * 4), Bhi + go);            \
            cp_async16(smem_u32(sBl + r * PSTR + c * 4), Blo + go);            \
        }                                                                      \
    };                                                                         \
    _Pragma("unroll")                                                          \
    for (int s = 0; s < GSTAGES - 1; s++) { load_stage(s, s); cp_commit(); }   \
    for (int cch = 0; cch < NCHUNK; cch++) {                                   \
        __syncthreads();                                                       \
        const int lc = cch + GSTAGES - 1;                                      \
        if (lc < NCHUNK) load_stage(lc % GSTAGES, lc);                         \
        cp_commit();                                                           \
        cp_wait<GSTAGES - 2>();                                                \
        __syncthreads();                                                       \
        const uint32_t* sAh = smu + (cch % GSTAGES) * STAGE_U + (wm * 64) * PSTR; \
        const uint32_t* sAl = sAh + A_PL;                                      \
        const uint32_t* sBh = smu + (cch % GSTAGES) * STAGE_U + 2 * A_PL + (wn * 64) * PSTR; \
        const uint32_t* sBl = sBh + B_PL;                                      \
        _Pragma("unroll")                                                      \
        for (int ks = 0; ks < 2; ks++) {                                       \
            const int kb = ks * 8 + q;                                         \
            uint32_t bhi[8][2], blo[8][2];                                     \
            _Pragma("unroll")                                                  \
            for (int ni = 0; ni < 8; ni++) {                                   \
                const int nrow = (ni * 8 + g) * PSTR;                          \
                bhi[ni][0] = sBh[nrow + kb];                                   \
                bhi[ni][1] = sBh[nrow + kb + 4];                               \
                blo[ni][0] = sBl[nrow + kb];                                   \
                blo[ni][1] = sBl[nrow + kb + 4];                               \
            }                                                                  \
            _Pragma("unroll")                                                  \
            for (int mi = 0; mi < 4; mi++) {                                   \
                const int r0i = (mi * 16 + g) * PSTR;                          \
                const int r1i = r0i + 8 * PSTR;                                \
                uint32_t ahi[4], alo[4];                                       \
                ahi[0] = sAh[r0i + kb];     ahi[1] = sAh[r1i + kb];            \
                ahi[2] = sAh[r0i + kb + 4]; ahi[3] = sAh[r1i + kb + 4];        \
                alo[0] = sAl[r0i + kb];     alo[1] = sAl[r1i + kb];            \
                alo[2] = sAl[r0i + kb + 4]; alo[3] = sAl[r1i + kb + 4];        \
                _Pragma("unroll")                                              \
                for (int ni = 0; ni < 8; ni++) mma_bf16(acc[mi][ni], ahi, bhi[ni]); \
                _Pragma("unroll")                                              \
                for (int ni = 0; ni < 8; ni++) mma_bf16(acc[mi][ni], alo, bhi[ni]); \
                _Pragma("unroll")                                              \
                for (int ni = 0; ni < 8; ni++) mma_bf16(acc[mi][ni], ahi, blo[ni]); \
            }                                                                  \
        }                                                                      \
    }

// Fused QKV GEMM: C[8192, 6144] vs fused weights; epilogue routes per 2048-col
// block: Q -> planes, K -> planes, V -> fp32.
__global__ void __launch_bounds__(256, 1) gemm_qkv(
    const uint32_t* __restrict__ Ahi, const uint32_t* __restrict__ Alo,
    const uint32_t* __restrict__ Bhi, const uint32_t* __restrict__ Blo,
    uint32_t* __restrict__ Qh, uint32_t* __restrict__ Ql,
    uint32_t* __restrict__ Kh, uint32_t* __restrict__ Kl,
    float* __restrict__ V)
{
    extern __shared__ uint32_t smu[];
    const int t  = threadIdx.x;
    const int w  = t >> 5;
    const int l  = t & 31;
    const int g  = l >> 2;
    const int q  = l & 3;
    const int wm = w >> 2;
    const int wn = w & 3;
    const int bm = blockIdx.y * GBM;
    const int bn = blockIdx.x * GBN;          // 0..5888

    GEMM_MAINLOOP(Ahi, Alo, Bhi, Blo)

    const int which = blockIdx.x >> 3;        // 0=Q, 1=K, 2=V
    const int xb    = blockIdx.x & 7;
#pragma unroll
    for (int mi = 0; mi < 4; mi++) {
        const int r0 = bm + wm * 64 + mi * 16 + g;
        if (which == 2) {
#pragma unroll
            for (int ni = 0; ni < 8; ni++) {
                const int col = xb * 256 + wn * 64 + ni * 8 + q * 2;
                *(float2*)&V[(size_t)r0 * D_MODEL + col] =
                    make_float2(acc[mi][ni][0], acc[mi][ni][1]);
                *(float2*)&V[(size_t)(r0 + 8) * D_MODEL + col] =
                    make_float2(acc[mi][ni][2], acc[mi][ni][3]);
            }
        } else {
            uint32_t* ph = (which == 0) ? Qh : Kh;
            uint32_t* pl = (which == 0) ? Ql : Kl;
#pragma unroll
            for (int ni = 0; ni < 8; ni++) {
                const int pidx = xb * 128 + wn * 32 + ni * 4 + q;
                uint32_t h0, l0, h1, l1;
                split2(make_float2(acc[mi][ni][0], acc[mi][ni][1]), h0, l0);
                split2(make_float2(acc[mi][ni][2], acc[mi][ni][3]), h1, l1);
                ph[(size_t)r0 * KW + pidx]       = h0;
                pl[(size_t)r0 * KW + pidx]       = l0;
                ph[(size_t)(r0 + 8) * KW + pidx] = h1;
                pl[(size_t)(r0 + 8) * KW + pidx] = l1;
            }
        }
    }
}

// Plain GEMM (fp32 C out): used for the final AO @ Wo^T.
__global__ void __launch_bounds__(256, 1) gemm_pre(
    const uint32_t* __restrict__ Ahi, const uint32_t* __restrict__ Alo,
    const uint32_t* __restrict__ Bhi, const uint32_t* __restrict__ Blo,
    float* __restrict__ C)
{
    extern __shared__ uint32_t smu[];
    const int t  = threadIdx.x;
    const int w  = t >> 5;
    const int l  = t & 31;
    const int g  = l >> 2;
    const int q  = l & 3;
    const int wm = w >> 2;
    const int wn = w & 3;
    const int bm = blockIdx.y * GBM;
    const int bn = blockIdx.x * GBN;

    GEMM_MAINLOOP(Ahi, Alo, Bhi, Blo)

#pragma unroll
    for (int mi = 0; mi < 4; mi++) {
        const int r0 = bm + wm * 64 + mi * 16 + g;
#pragma unroll
        for (int ni = 0; ni < 8; ni++) {
            const int col = bn + wn * 64 + ni * 8 + q * 2;
            *(float2*)&C[(size_t)r0 * D_MODEL + col] =
                make_float2(acc[mi][ni][0], acc[mi][ni][1]);
            *(float2*)&C[(size_t)(r0 + 8) * D_MODEL + col] =
                make_float2(acc[mi][ni][2], acc[mi][ni][3]);
        }
    }
}

// ---------------------------------------------------------------------------
// Tensorized flash attention (causal), mma.sync bf16x3.  Epilogue writes
// AO hi/lo planes directly (consumed by the final GEMM).
// ---------------------------------------------------------------------------
#define AT_THREADS 128
#define QKSTR 68
#define VSTR  136
#define SQH 0
#define SQL (SQH + 64 * QKSTR)
#define SKH (SQL + 64 * QKSTR)
#define SKL (SKH + 64 * QKSTR)
#define SVH (SKL + 64 * QKSTR)
#define SVL (SVH + 32 * VSTR)
#define AT_SMEM_U (SVL + 32 * VSTR)
#define AT_SMEM_BYTES (AT_SMEM_U * 4)   // 104448
#define NEG_BIG (-1.0e30f)

__global__ void __launch_bounds__(AT_THREADS, 2) attn_mma(
    const uint32_t* __restrict__ Qh, const uint32_t* __restrict__ Ql,
    const uint32_t* __restrict__ Kh, const uint32_t* __restrict__ Kl,
    const float* __restrict__ V,
    uint32_t* __restrict__ AOh, uint32_t* __restrict__ AOl)
{
    extern __shared__ uint32_t su[];
    uint32_t* qh_s = su + SQH;
    uint32_t* ql_s = su + SQL;
    uint32_t* kh_s = su + SKH;
    uint32_t* kl_s = su + SKL;
    uint32_t* vh_s = su + SVH;
    uint32_t* vl_s = su + SVL;

    const int t  = threadIdx.x;
    const int w  = t >> 5;
    const int l  = t & 31;
    const int g  = l >> 2;
    const int q  = l & 3;
    const int bh = blockIdx.y;
    const int b  = bh >> 4;
    const int h  = bh & 15;
    const int mt = gridDim.x - 1 - blockIdx.x;
    const float scale = 0.088388347648318447f;

    {
        const size_t prow0 = (size_t)b * SEQ + mt * 64;
        const int pcol = h * 64;
#pragma unroll
        for (int it = 0; it < 8; it++) {
            const int idx = it * AT_THREADS + t;
            const int r = idx >> 4;
            const int c4 = (idx & 15) * 4;
            *(uint4*)&qh_s[r * QKSTR + c4] =
                *(const uint4*)&Qh[(prow0 + r) * KW + pcol + c4];
            *(uint4*)&ql_s[r * QKSTR + c4] =
                *(const uint4*)&Ql[(prow0 + r) * KW + pcol + c4];
        }
    }

    float o[16][4];
#pragma unroll
    for (int n2 = 0; n2 < 16; n2++)
#pragma unroll
        for (int c = 0; c < 4; c++) o[n2][c] = 0.0f;
    float m_A = NEG_BIG, m_B = NEG_BIG, l_A = 0.0f, l_B = 0.0f;

    const int rowA = mt * 64 + 16 * w + g;
    const int rowB = rowA + 8;

    for (int nt = 0; nt <= mt; nt++) {
        __syncthreads();
        {
            const size_t krow0 = (size_t)b * SEQ + nt * 64;
            const int pcol = h * 64;
#pragma unroll
            for (int it = 0; it < 8; it++) {
                const int idx = it * AT_THREADS + t;
                const int r = idx >> 4;
                const int c4 = (idx & 15) * 4;
                *(uint4*)&kh_s[r * QKSTR + c4] =
                    *(const uint4*)&Kh[(krow0 + r) * KW + pcol + c4];
                *(uint4*)&kl_s[r * QKSTR + c4] =
                    *(const uint4*)&Kl[(krow0 + r) * KW + pcol + c4];
            }
            const size_t vbase = ((size_t)b * SEQ + nt * 64) * D_MODEL + h * DHEAD;
#pragma unroll 8
            for (int kp = 0; kp < 32; kp++) {
                const float v0 = V[vbase + (size_t)(2 * kp)     * D_MODEL + t];
                const float v1 = V[vbase + (size_t)(2 * kp + 1) * D_MODEL + t];
                uint32_t hi, lo;
                split2(make_float2(v0, v1), hi, lo);
                vh_s[kp * VSTR + t] = hi;
                vl_s[kp * VSTR + t] = lo;
            }
        }
        __syncthreads();

        float s[8][4];
#pragma unroll
        for (int j = 0; j < 8; j++)
#pragma unroll
            for (int c = 0; c < 4; c++) s[j][c] = 0.0f;

        const int arow0 = (16 * w + g) * QKSTR;
        const int arow1 = arow0 + 8 * QKSTR;
#pragma unroll
        for (int c = 0; c < 8; c++) {
            const int kcol = 8 * c + q;
            uint32_t a_h[4], a_l[4];
            a_h[0] = qh_s[arow0 + kcol];     a_h[1] = qh_s[arow1 + kcol];
            a_h[2] = qh_s[arow0 + kcol + 4]; a_h[3] = qh_s[arow1 + kcol + 4];
            a_l[0] = ql_s[arow0 + kcol];     a_l[1] = ql_s[arow1 + kcol];
            a_l[2] = ql_s[arow0 + kcol + 4]; a_l[3] = ql_s[arow1 + kcol + 4];
#pragma unroll
            for (int j = 0; j < 8; j++) {
                const int brow = (8 * j + g) * QKSTR;
                uint32_t b_h[2] = { kh_s[brow + kcol], kh_s[brow + kcol + 4] };
                uint32_t b_l[2] = { kl_s[brow + kcol], kl_s[brow + kcol + 4] };
                mma_bf16(s[j], a_h, b_h);
                mma_bf16(s[j], a_l, b_h);
                mma_bf16(s[j], a_h, b_l);
            }
        }

        const bool diag = (nt == mt);
#pragma unroll
        for (int j = 0; j < 8; j++) {
            s[j][0] *= scale; s[j][1] *= scale;
            s[j][2] *= scale; s[j][3] *= scale;
            if (diag) {
                const int col = nt * 64 + 8 * j + 2 * q;
                if (col     > rowA) s[j][0] = NEG_BIG;
                if (col + 1 > rowA) s[j][1] = NEG_BIG;
                if (col     > rowB) s[j][2] = NEG_BIG;
                if (col + 1 > rowB) s[j][3] = NEG_BIG;
            }
        }

        float mxA = NEG_BIG, mxB = NEG_BIG;
#pragma unroll
        for (int j = 0; j < 8; j++) {
            mxA = fmaxf(mxA, fmaxf(s[j][0], s[j][1]));
            mxB = fmaxf(mxB, fmaxf(s[j][2], s[j][3]));
        }
        mxA = fmaxf(mxA, __shfl_xor_sync(0xffffffffu, mxA, 1));
        mxA = fmaxf(mxA, __shfl_xor_sync(0xffffffffu, mxA, 2));
        mxB = fmaxf(mxB, __shfl_xor_sync(0xffffffffu, mxB, 1));
        mxB = fmaxf(mxB, __shfl_xor_sync(0xffffffffu, mxB, 2));

        const float mAn = fmaxf(m_A, mxA);
        const float mBn = fmaxf(m_B, mxB);
        const float alA = __expf(m_A - mAn);
        const float alB = __expf(m_B - mBn);
        m_A = mAn; m_B = mBn;

        float smA = 0.0f, smB = 0.0f;
#pragma unroll
        for (int j = 0; j < 8; j++) {
            s[j][0] = __expf(s[j][0] - m_A);
            s[j][1] = __expf(s[j][1] - m_A);
            s[j][2] = __expf(s[j][2] - m_B);
            s[j][3] = __expf(s[j][3] - m_B);
            smA += s[j][0] + s[j][1];
            smB += s[j][2] + s[j][3];
        }
        smA += __shfl_xor_sync(0xffffffffu, smA, 1);
        smA += __shfl_xor_sync(0xffffffffu, smA, 2);
        smB += __shfl_xor_sync(0xffffffffu, smB, 1);
        smB += __shfl_xor_sync(0xffffffffu, smB, 2);
        l_A = l_A * alA + smA;
        l_B = l_B * alB + smB;

#pragma unroll
        for (int n2 = 0; n2 < 16; n2++) {
            o[n2][0] *= alA; o[n2][1] *= alA;
            o[n2][2] *= alB; o[n2][3] *= alB;
        }

        uint32_t p_h[4][4], p_l[4][4];
#pragma unroll
        for (int c = 0; c < 4; c++) {
            split2(make_float2(s[2 * c][0],     s[2 * c][1]),     p_h[c][0], p_l[c][0]);
            split2(make_float2(s[2 * c][2],     s[2 * c][3]),     p_h[c][1], p_l[c][1]);
            split2(make_float2(s[2 * c + 1][0], s[2 * c + 1][1]), p_h[c][2], p_l[c][2]);
            split2(make_float2(s[2 * c + 1][2], s[2 * c + 1][3]), p_h[c][3], p_l[c][3]);
        }

#pragma unroll
        for (int n2 = 0; n2 < 16; n2++) {
            const int vcol = 8 * n2 + g;
#pragma unroll
            for (int c = 0; c < 4; c++) {
                const int kp0 = 8 * c + q;
                uint32_t v_h[2] = { vh_s[kp0 * VSTR + vcol], vh_s[(kp0 + 4) * VSTR + vcol] };
                uint32_t v_l[2] = { vl_s[kp0 * VSTR + vcol], vl_s[(kp0 + 4) * VSTR + vcol] };
                mma_bf16(o[n2], p_h[c], v_h);
                mma_bf16(o[n2], p_l[c], v_h);
                mma_bf16(o[n2], p_h[c], v_l);
            }
        }
    }

    // ---- epilogue: write AO hi/lo planes directly ----
    const float invA = 1.0f / l_A;
    const float invB = 1.0f / l_B;
    const size_t prow = (size_t)b * SEQ;
#pragma unroll
    for (int n2 = 0; n2 < 16; n2++) {
        const int pidx = h * 64 + 4 * n2 + q;
        uint32_t h0, l0, h1, l1;
        split2(make_float2(o[n2][0] * invA, o[n2][1] * invA), h0, l0);
        split2(make_float2(o[n2][2] * invB, o[n2][3] * invB), h1, l1);
        AOh[(prow + rowA) * KW + pidx] = h0;
        AOl[(prow + rowA) * KW + pidx] = l0;
        AOh[(prow + rowB) * KW + pidx] = h1;
        AOl[(prow + rowB) * KW + pidx] = l1;
    }
}

// ---------------------------------------------------------------------------
// Launcher
// ---------------------------------------------------------------------------
extern "C" void kernel_launch(void* const* d_in, const int* in_sizes, int n_in,
                              void* d_out, int out_size)
{
    const float* x  = (const float*)d_in[0];
    const float* Wq = (const float*)d_in[1];
    const float* Wk = (const float*)d_in[2];
    const float* Wv = (const float*)d_in[3];
    const float* Wo = (const float*)d_in[4];
    float* out = (float*)d_out;

    void *pV, *pXh, *pXl, *pWh, *pWl, *pQh, *pQl, *pKh, *pKl;
    cudaGetSymbolAddress(&pV,  g_V);
    cudaGetSymbolAddress(&pXh, g_Xhi);
    cudaGetSymbolAddress(&pXl, g_Xlo);
    cudaGetSymbolAddress(&pWh, g_Whi);
    cudaGetSymbolAddress(&pWl, g_Wlo);
    cudaGetSymbolAddress(&pQh, g_QPh);
    cudaGetSymbolAddress(&pQl, g_QPl);
    cudaGetSymbolAddress(&pKh, g_KPh);
    cudaGetSymbolAddress(&pKl, g_KPl);

    uint32_t* Xh = (uint32_t*)pXh; uint32_t* Xl = (uint32_t*)pXl;
    uint32_t* Wh = (uint32_t*)pWh; uint32_t* Wl = (uint32_t*)pWl;

    cudaFuncSetAttribute(gemm_qkv,
                         cudaFuncAttributeMaxDynamicSharedMemorySize, GEMM_SMEM_BYTES);
    cudaFuncSetAttribute(gemm_pre,
                         cudaFuncAttributeMaxDynamicSharedMemorySize, GEMM_SMEM_BYTES);
    cudaFuncSetAttribute(attn_mma,
                         cudaFuncAttributeMaxDynamicSharedMemorySize, AT_SMEM_BYTES);

    const int n2x = MROWS * D_MODEL / 2;      // 8388608
    const int n2w = D_MODEL * D_MODEL / 2;    // 2097152

    // splits: x and fused weights
    split_kernel<<<n2x / 256, 256>>>(x, Xh, Xl, n2x);
    split_kernel<<<n2w / 256, 256>>>(Wq, Wh,            Wl,            n2w);
    split_kernel<<<n2w / 256, 256>>>(Wk, Wh + (size_t)n2w,     Wl + (size_t)n2w,     n2w);
    split_kernel<<<n2w / 256, 256>>>(Wv, Wh + (size_t)2 * n2w, Wl + (size_t)2 * n2w, n2w);

    // fused QKV projection: [8192, 6144]
    const dim3 qkv_grid(3 * D_MODEL / GBN, MROWS / GBM);  // (24, 64)
    gemm_qkv<<<qkv_grid, 256, GEMM_SMEM_BYTES>>>(
        Xh, Xl, Wh, Wl,
        (uint32_t*)pQh, (uint32_t*)pQl, (uint32_t*)pKh, (uint32_t*)pKl,
        (float*)pV);

    // attention (writes AO planes into Xh/Xl — x planes no longer needed)
    const dim3 attn_grid(SEQ / 64, BATCH * NHEADS);       // (32, 64)
    attn_mma<<<attn_grid, AT_THREADS, AT_SMEM_BYTES>>>(
        (const uint32_t*)pQh, (const uint32_t*)pQl,
        (const uint32_t*)pKh, (const uint32_t*)pKl,
        (const float*)pV, Xh, Xl);

    // Wo planes (reuse slice 0 of the weight plane buffers)
    split_kernel<<<n2w / 256, 256>>>(Wo, Wh, Wl, n2w);

    // final projection: out = AO @ Wo^T
    const dim3 ogrid(D_MODEL / GBN, MROWS / GBM);         // (8, 64)
    gemm_pre<<<ogrid, 256, GEMM_SMEM_BYTES>>>(Xh, Xl, Wh, Wl, out);
}

// round 14
// speedup vs baseline: 1.9270x; 1.2872x over previous
#include <cuda_runtime.h>
#include <cuda_bf16.h>
#include <cuda_fp16.h>
#include <cstdint>
#include <math.h>

// ============================================================================
// StandardAttention, B=4, S=2048, D=2048, H=16, Dh=128, fp32.
// R14: projection GEMMs switch bf16x3 -> fp16x2:
//      (a_hi + a_lo)*b_hi  ==  full-precision A x fp16(B), unbiased ~2^-12.
//      2 MMAs/fragment instead of 3 (-33% of the 2.9ms GEMM share); B lo
//      plane never loaded. Attention unchanged (bf16x3); its epilogue now
//      emits fp16 AO planes for the final GEMM.
// ============================================================================

#define D_MODEL 2048
#define SEQ     2048
#define BATCH   4
#define NHEADS  16
#define DHEAD   128
#define MROWS   (BATCH * SEQ)          // 8192

__device__ float    g_V  [ (size_t)MROWS * D_MODEL ];
__device__ uint32_t g_Xhi[ (size_t)MROWS * D_MODEL / 2 ];   // x planes, then AO planes (fp16)
__device__ uint32_t g_Xlo[ (size_t)MROWS * D_MODEL / 2 ];
__device__ uint32_t g_Whi[ (size_t)3 * D_MODEL * D_MODEL / 2 ]; // fp16 hi; Wo reuses slice 0
__device__ uint32_t g_Wlo[ (size_t)3 * D_MODEL * D_MODEL / 2 ]; // written, unused by GEMM
__device__ uint32_t g_QPh[ (size_t)MROWS * D_MODEL / 2 ];   // bf16 planes for attention
__device__ uint32_t g_QPl[ (size_t)MROWS * D_MODEL / 2 ];
__device__ uint32_t g_KPh[ (size_t)MROWS * D_MODEL / 2 ];
__device__ uint32_t g_KPl[ (size_t)MROWS * D_MODEL / 2 ];

// ---------------------------------------------------------------------------
// Helpers
// ---------------------------------------------------------------------------
__device__ __forceinline__ uint32_t smem_u32(const void* p) {
    uint32_t a;
    asm("{ .reg .u64 t; cvta.to.shared.u64 t, %1; cvt.u32.u64 %0, t; }"
        : "=r"(a) : "l"(p));
    return a;
}
__device__ __forceinline__ void cp_async16(uint32_t dst, const void* src) {
    asm volatile("cp.async.cg.shared.global [%0], [%1], 16;"
                 :: "r"(dst), "l"(src) : "memory");
}
__device__ __forceinline__ void cp_commit() {
    asm volatile("cp.async.commit_group;" ::: "memory");
}
template<int N> __device__ __forceinline__ void cp_wait() {
    asm volatile("cp.async.wait_group %0;" :: "n"(N) : "memory");
}

__device__ __forceinline__ void mma_bf16(float* d, const uint32_t* a,
                                         const uint32_t* b) {
    asm volatile(
        "mma.sync.aligned.m16n8k16.row.col.f32.bf16.bf16.f32 "
        "{%0,%1,%2,%3}, {%4,%5,%6,%7}, {%8,%9}, {%0,%1,%2,%3};"
        : "+f"(d[0]), "+f"(d[1]), "+f"(d[2]), "+f"(d[3])
        : "r"(a[0]), "r"(a[1]), "r"(a[2]), "r"(a[3]), "r"(b[0]), "r"(b[1]));
}
__device__ __forceinline__ void mma_f16(float* d, const uint32_t* a,
                                        const uint32_t* b) {
    asm volatile(
        "mma.sync.aligned.m16n8k16.row.col.f32.f16.f16.f32 "
        "{%0,%1,%2,%3}, {%4,%5,%6,%7}, {%8,%9}, {%0,%1,%2,%3};"
        : "+f"(d[0]), "+f"(d[1]), "+f"(d[2]), "+f"(d[3])
        : "r"(a[0]), "r"(a[1]), "r"(a[2]), "r"(a[3]), "r"(b[0]), "r"(b[1]));
}

// bf16 split (attention-internal: P, V, Q/K plane production)
__device__ __forceinline__ void split2(float2 v, uint32_t& hi, uint32_t& lo) {
    asm("cvt.rn.bf16x2.f32 %0, %1, %2;" : "=r"(hi) : "f"(v.y), "f"(v.x));
    const float hx = __uint_as_float(hi << 16);
    const float hy = __uint_as_float(hi & 0xffff0000u);
    const float lx = v.x - hx;
    const float ly = v.y - hy;
    asm("cvt.rn.bf16x2.f32 %0, %1, %2;" : "=r"(lo) : "f"(ly), "f"(lx));
}

// fp16 split (GEMM operand planes): hi = f16x2_rn(v), lo = f16x2_rn(v - hi)
__device__ __forceinline__ void split2_f16(float2 v, uint32_t& hi, uint32_t& lo) {
    asm("cvt.rn.f16x2.f32 %0, %1, %2;" : "=r"(hi) : "f"(v.y), "f"(v.x));
    float hx, hy;
    asm("{ .reg .f16 a, b; mov.b32 {a, b}, %2;"
        " cvt.f32.f16 %0, a; cvt.f32.f16 %1, b; }"
        : "=f"(hx), "=f"(hy) : "r"(hi));
    const float lx = v.x - hx;
    const float ly = v.y - hy;
    asm("cvt.rn.f16x2.f32 %0, %1, %2;" : "=r"(lo) : "f"(ly), "f"(lx));
}

// ---------------------------------------------------------------------------
// Pre-split kernel: fp32 -> packed f16x2 hi/lo planes.
// ---------------------------------------------------------------------------
__global__ void __launch_bounds__(256) split_f16_kernel(
    const float* __restrict__ src, uint32_t* __restrict__ hi,
    uint32_t* __restrict__ lo, int n2)
{
    const int i = blockIdx.x * 256 + threadIdx.x;
    if (i < n2) {
        const float2 v = ((const float2*)src)[i];
        uint32_t h, l;
        split2_f16(v, h, l);
        hi[i] = h;
        lo[i] = l;
    }
}

// ---------------------------------------------------------------------------
// GEMM common: fp16x2, 256 threads, CTA 128x256, BK=32, 3-stage cp.async.
// Stage holds A hi, A lo, B hi (B lo not needed). PSTR=20: conflict-free.
// ---------------------------------------------------------------------------
#define GBM 128
#define GBN 256
#define GBK 32
#define GSTAGES 3
#define NCHUNK (D_MODEL / GBK)          // 64
#define KW   (D_MODEL / 2)              // 1024 u32 per plane row
#define PSTR 20
#define A_PL (GBM * PSTR)               // 2560
#define B_PL (GBN * PSTR)               // 5120
#define STAGE_U (2 * A_PL + B_PL)       // 10240
#define GEMM_SMEM_BYTES (GSTAGES * STAGE_U * 4)   // 122880

#define GEMM_MAINLOOP(Ahi, Alo, Bhi)                                           \
    float acc[4][8][4];                                                        \
    _Pragma("unroll")                                                          \
    for (int mi = 0; mi < 4; mi++)                                             \
        _Pragma("unroll")                                                      \
        for (int ni = 0; ni < 8; ni++)                                         \
            _Pragma("unroll")                                                  \
            for (int cc = 0; cc < 4; cc++) acc[mi][ni][cc] = 0.0f;             \
    auto load_stage = [&](int s, int chunk) {                                  \
        uint32_t* sAh = smu + s * STAGE_U;                                     \
        uint32_t* sAl = sAh + A_PL;                                            \
        uint32_t* sBh = sAl + A_PL;                                            \
        const int col0 = chunk * 16;                                           \
        _Pragma("unroll")                                                      \
        for (int i = 0; i < 2; i++) {                                          \
            const int idx = i * 256 + t, r = idx >> 2, c = idx & 3;            \
            const size_t go = (size_t)(bm + r) * KW + col0 + c * 4;            \
            cp_async16(smem_u32(sAh + r * PSTR + c * 4), Ahi + go);            \
            cp_async16(smem_u32(sAl + r * PSTR + c * 4), Alo + go);            \
        }                                                                      \
        _Pragma("unroll")                                                      \
        for (int i = 0; i < 4; i++) {                                          \
            const int idx = i * 256 + t, r = idx >> 2, c = idx & 3;            \
            const size_t go = (size_t)(bn + r) * KW + col0 + c * 4;            \
            cp_async16(smem_u32(sBh + r * PSTR + c * 4), Bhi + go);            \
        }                                                                      \
    };                                                                         \
    _Pragma("unroll")                                                          \
    for (int s = 0; s < GSTAGES - 1; s++) { load_stage(s, s); cp_commit(); }   \
    for (int cch = 0; cch < NCHUNK; cch++) {                                   \
        __syncthreads();                                                       \
        const int lc = cch + GSTAGES - 1;                                      \
        if (lc < NCHUNK) load_stage(lc % GSTAGES, lc);                         \
        cp_commit();                                                           \
        cp_wait<GSTAGES - 2>();                                                \
        __syncthreads();                                                       \
        const uint32_t* sAh = smu + (cch % GSTAGES) * STAGE_U + (wm * 64) * PSTR; \
        const uint32_t* sAl = sAh + A_PL;                                      \
        const uint32_t* sBh = smu + (cch % GSTAGES) * STAGE_U + 2 * A_PL + (wn * 64) * PSTR; \
        _Pragma("unroll")                                                      \
        for (int ks = 0; ks < 2; ks++) {                                       \
            const int kb = ks * 8 + q;                                         \
            uint32_t bhi[8][2];                                                \
            _Pragma("unroll")                                                  \
            for (int ni = 0; ni < 8; ni++) {                                   \
                const int nrow = (ni * 8 + g) * PSTR;                          \
                bhi[ni][0] = sBh[nrow + kb];                                   \
                bhi[ni][1] = sBh[nrow + kb + 4];                               \
            }                                                                  \
            _Pragma("unroll")                                                  \
            for (int mi = 0; mi < 4; mi++) {                                   \
                const int r0i = (mi * 16 + g) * PSTR;                          \
                const int r1i = r0i + 8 * PSTR;                                \
                uint32_t ahi[4], alo[4];                                       \
                ahi[0] = sAh[r0i + kb];     ahi[1] = sAh[r1i + kb];            \
                ahi[2] = sAh[r0i + kb + 4]; ahi[3] = sAh[r1i + kb + 4];        \
                alo[0] = sAl[r0i + kb];     alo[1] = sAl[r1i + kb];            \
                alo[2] = sAl[r0i + kb + 4]; alo[3] = sAl[r1i + kb + 4];        \
                _Pragma("unroll")                                              \
                for (int ni = 0; ni < 8; ni++) mma_f16(acc[mi][ni], ahi, bhi[ni]); \
                _Pragma("unroll")                                              \
                for (int ni = 0; ni < 8; ni++) mma_f16(acc[mi][ni], alo, bhi[ni]); \
            }                                                                  \
        }                                                                      \
    }

// Fused QKV GEMM: C[8192, 6144]; epilogue: Q/K -> bf16 planes, V -> fp32.
__global__ void __launch_bounds__(256, 1) gemm_qkv(
    const uint32_t* __restrict__ Ahi, const uint32_t* __restrict__ Alo,
    const uint32_t* __restrict__ Bhi,
    uint32_t* __restrict__ Qh, uint32_t* __restrict__ Ql,
    uint32_t* __restrict__ Kh, uint32_t* __restrict__ Kl,
    float* __restrict__ V)
{
    extern __shared__ uint32_t smu[];
    const int t  = threadIdx.x;
    const int w  = t >> 5;
    const int l  = t & 31;
    const int g  = l >> 2;
    const int q  = l & 3;
    const int wm = w >> 2;
    const int wn = w & 3;
    const int bm = blockIdx.y * GBM;
    const int bn = blockIdx.x * GBN;

    GEMM_MAINLOOP(Ahi, Alo, Bhi)

    const int which = blockIdx.x >> 3;        // 0=Q, 1=K, 2=V
    const int xb    = blockIdx.x & 7;
#pragma unroll
    for (int mi = 0; mi < 4; mi++) {
        const int r0 = bm + wm * 64 + mi * 16 + g;
        if (which == 2) {
#pragma unroll
            for (int ni = 0; ni < 8; ni++) {
                const int col = xb * 256 + wn * 64 + ni * 8 + q * 2;
                *(float2*)&V[(size_t)r0 * D_MODEL + col] =
                    make_float2(acc[mi][ni][0], acc[mi][ni][1]);
                *(float2*)&V[(size_t)(r0 + 8) * D_MODEL + col] =
                    make_float2(acc[mi][ni][2], acc[mi][ni][3]);
            }
        } else {
            uint32_t* ph = (which == 0) ? Qh : Kh;
            uint32_t* pl = (which == 0) ? Ql : Kl;
#pragma unroll
            for (int ni = 0; ni < 8; ni++) {
                const int pidx = xb * 128 + wn * 32 + ni * 4 + q;
                uint32_t h0, l0, h1, l1;
                split2(make_float2(acc[mi][ni][0], acc[mi][ni][1]), h0, l0);
                split2(make_float2(acc[mi][ni][2], acc[mi][ni][3]), h1, l1);
                ph[(size_t)r0 * KW + pidx]       = h0;
                pl[(size_t)r0 * KW + pidx]       = l0;
                ph[(size_t)(r0 + 8) * KW + pidx] = h1;
                pl[(size_t)(r0 + 8) * KW + pidx] = l1;
            }
        }
    }
}

// Plain GEMM (fp32 C out): final AO @ Wo^T.
__global__ void __launch_bounds__(256, 1) gemm_pre(
    const uint32_t* __restrict__ Ahi, const uint32_t* __restrict__ Alo,
    const uint32_t* __restrict__ Bhi,
    float* __restrict__ C)
{
    extern __shared__ uint32_t smu[];
    const int t  = threadIdx.x;
    const int w  = t >> 5;
    const int l  = t & 31;
    const int g  = l >> 2;
    const int q  = l & 3;
    const int wm = w >> 2;
    const int wn = w & 3;
    const int bm = blockIdx.y * GBM;
    const int bn = blockIdx.x * GBN;

    GEMM_MAINLOOP(Ahi, Alo, Bhi)

#pragma unroll
    for (int mi = 0; mi < 4; mi++) {
        const int r0 = bm + wm * 64 + mi * 16 + g;
#pragma unroll
        for (int ni = 0; ni < 8; ni++) {
            const int col = bn + wn * 64 + ni * 8 + q * 2;
            *(float2*)&C[(size_t)r0 * D_MODEL + col] =
                make_float2(acc[mi][ni][0], acc[mi][ni][1]);
            *(float2*)&C[(size_t)(r0 + 8) * D_MODEL + col] =
                make_float2(acc[mi][ni][2], acc[mi][ni][3]);
        }
    }
}

// ---------------------------------------------------------------------------
// Tensorized flash attention (causal), mma.sync bf16x3 — unchanged from R13
// except the AO epilogue emits fp16 planes (for the fp16 final GEMM).
// ---------------------------------------------------------------------------
#define AT_THREADS 128
#define QKSTR 68
#define VSTR  136
#define SQH 0
#define SQL (SQH + 64 * QKSTR)
#define SKH (SQL + 64 * QKSTR)
#define SKL (SKH + 64 * QKSTR)
#define SVH (SKL + 64 * QKSTR)
#define SVL (SVH + 32 * VSTR)
#define AT_SMEM_U (SVL + 32 * VSTR)
#define AT_SMEM_BYTES (AT_SMEM_U * 4)   // 104448
#define NEG_BIG (-1.0e30f)

__global__ void __launch_bounds__(AT_THREADS, 2) attn_mma(
    const uint32_t* __restrict__ Qh, const uint32_t* __restrict__ Ql,
    const uint32_t* __restrict__ Kh, const uint32_t* __restrict__ Kl,
    const float* __restrict__ V,
    uint32_t* __restrict__ AOh, uint32_t* __restrict__ AOl)
{
    extern __shared__ uint32_t su[];
    uint32_t* qh_s = su + SQH;
    uint32_t* ql_s = su + SQL;
    uint32_t* kh_s = su + SKH;
    uint32_t* kl_s = su + SKL;
    uint32_t* vh_s = su + SVH;
    uint32_t* vl_s = su + SVL;

    const int t  = threadIdx.x;
    const int w  = t >> 5;
    const int l  = t & 31;
    const int g  = l >> 2;
    const int q  = l & 3;
    const int bh = blockIdx.y;
    const int b  = bh >> 4;
    const int h  = bh & 15;
    const int mt = gridDim.x - 1 - blockIdx.x;
    const float scale = 0.088388347648318447f;

    {
        const size_t prow0 = (size_t)b * SEQ + mt * 64;
        const int pcol = h * 64;
#pragma unroll
        for (int it = 0; it < 8; it++) {
            const int idx = it * AT_THREADS + t;
            const int r = idx >> 4;
            const int c4 = (idx & 15) * 4;
            *(uint4*)&qh_s[r * QKSTR + c4] =
                *(const uint4*)&Qh[(prow0 + r) * KW + pcol + c4];
            *(uint4*)&ql_s[r * QKSTR + c4] =
                *(const uint4*)&Ql[(prow0 + r) * KW + pcol + c4];
        }
    }

    float o[16][4];
#pragma unroll
    for (int n2 = 0; n2 < 16; n2++)
#pragma unroll
        for (int c = 0; c < 4; c++) o[n2][c] = 0.0f;
    float m_A = NEG_BIG, m_B = NEG_BIG, l_A = 0.0f, l_B = 0.0f;

    const int rowA = mt * 64 + 16 * w + g;
    const int rowB = rowA + 8;

    for (int nt = 0; nt <= mt; nt++) {
        __syncthreads();
        {
            const size_t krow0 = (size_t)b * SEQ + nt * 64;
            const int pcol = h * 64;
#pragma unroll
            for (int it = 0; it < 8; it++) {
                const int idx = it * AT_THREADS + t;
                const int r = idx >> 4;
                const int c4 = (idx & 15) * 4;
                *(uint4*)&kh_s[r * QKSTR + c4] =
                    *(const uint4*)&Kh[(krow0 + r) * KW + pcol + c4];
                *(uint4*)&kl_s[r * QKSTR + c4] =
                    *(const uint4*)&Kl[(krow0 + r) * KW + pcol + c4];
            }
            const size_t vbase = ((size_t)b * SEQ + nt * 64) * D_MODEL + h * DHEAD;
#pragma unroll 8
            for (int kp = 0; kp < 32; kp++) {
                const float v0 = V[vbase + (size_t)(2 * kp)     * D_MODEL + t];
                const float v1 = V[vbase + (size_t)(2 * kp + 1) * D_MODEL + t];
                uint32_t hi, lo;
                split2(make_float2(v0, v1), hi, lo);
                vh_s[kp * VSTR + t] = hi;
                vl_s[kp * VSTR + t] = lo;
            }
        }
        __syncthreads();

        float s[8][4];
#pragma unroll
        for (int j = 0; j < 8; j++)
#pragma unroll
            for (int c = 0; c < 4; c++) s[j][c] = 0.0f;

        const int arow0 = (16 * w + g) * QKSTR;
        const int arow1 = arow0 + 8 * QKSTR;
#pragma unroll
        for (int c = 0; c < 8; c++) {
            const int kcol = 8 * c + q;
            uint32_t a_h[4], a_l[4];
            a_h[0] = qh_s[arow0 + kcol];     a_h[1] = qh_s[arow1 + kcol];
            a_h[2] = qh_s[arow0 + kcol + 4]; a_h[3] = qh_s[arow1 + kcol + 4];
            a_l[0] = ql_s[arow0 + kcol];     a_l[1] = ql_s[arow1 + kcol];
            a_l[2] = ql_s[arow0 + kcol + 4]; a_l[3] = ql_s[arow1 + kcol + 4];
#pragma unroll
            for (int j = 0; j < 8; j++) {
                const int brow = (8 * j + g) * QKSTR;
                uint32_t b_h[2] = { kh_s[brow + kcol], kh_s[brow + kcol + 4] };
                uint32_t b_l[2] = { kl_s[brow + kcol], kl_s[brow + kcol + 4] };
                mma_bf16(s[j], a_h, b_h);
                mma_bf16(s[j], a_l, b_h);
                mma_bf16(s[j], a_h, b_l);
            }
        }

        const bool diag = (nt == mt);
#pragma unroll
        for (int j = 0; j < 8; j++) {
            s[j][0] *= scale; s[j][1] *= scale;
            s[j][2] *= scale; s[j][3] *= scale;
            if (diag) {
                const int col = nt * 64 + 8 * j + 2 * q;
                if (col     > rowA) s[j][0] = NEG_BIG;
                if (col + 1 > rowA) s[j][1] = NEG_BIG;
                if (col     > rowB) s[j][2] = NEG_BIG;
                if (col + 1 > rowB) s[j][3] = NEG_BIG;
            }
        }

        float mxA = NEG_BIG, mxB = NEG_BIG;
#pragma unroll
        for (int j = 0; j < 8; j++) {
            mxA = fmaxf(mxA, fmaxf(s[j][0], s[j][1]));
            mxB = fmaxf(mxB, fmaxf(s[j][2], s[j][3]));
        }
        mxA = fmaxf(mxA, __shfl_xor_sync(0xffffffffu, mxA, 1));
        mxA = fmaxf(mxA, __shfl_xor_sync(0xffffffffu, mxA, 2));
        mxB = fmaxf(mxB, __shfl_xor_sync(0xffffffffu, mxB, 1));
        mxB = fmaxf(mxB, __shfl_xor_sync(0xffffffffu, mxB, 2));

        const float mAn = fmaxf(m_A, mxA);
        const float mBn = fmaxf(m_B, mxB);
        const float alA = __expf(m_A - mAn);
        const float alB = __expf(m_B - mBn);
        m_A = mAn; m_B = mBn;

        float smA = 0.0f, smB = 0.0f;
#pragma unroll
        for (int j = 0; j < 8; j++) {
            s[j][0] = __expf(s[j][0] - m_A);
            s[j][1] = __expf(s[j][1] - m_A);
            s[j][2] = __expf(s[j][2] - m_B);
            s[j][3] = __expf(s[j][3] - m_B);
            smA += s[j][0] + s[j][1];
            smB += s[j][2] + s[j][3];
        }
        smA += __shfl_xor_sync(0xffffffffu, smA, 1);
        smA += __shfl_xor_sync(0xffffffffu, smA, 2);
        smB += __shfl_xor_sync(0xffffffffu, smB, 1);
        smB += __shfl_xor_sync(0xffffffffu, smB, 2);
        l_A = l_A * alA + smA;
        l_B = l_B * alB + smB;

#pragma unroll
        for (int n2 = 0; n2 < 16; n2++) {
            o[n2][0] *= alA; o[n2][1] *= alA;
            o[n2][2] *= alB; o[n2][3] *= alB;
        }

        uint32_t p_h[4][4], p_l[4][4];
#pragma unroll
        for (int c = 0; c < 4; c++) {
            split2(make_float2(s[2 * c][0],     s[2 * c][1]),     p_h[c][0], p_l[c][0]);
            split2(make_float2(s[2 * c][2],     s[2 * c][3]),     p_h[c][1], p_l[c][1]);
            split2(make_float2(s[2 * c + 1][0], s[2 * c + 1][1]), p_h[c][2], p_l[c][2]);
            split2(make_float2(s[2 * c + 1][2], s[2 * c + 1][3]), p_h[c][3], p_l[c][3]);
        }

#pragma unroll
        for (int n2 = 0; n2 < 16; n2++) {
            const int vcol = 8 * n2 + g;
#pragma unroll
            for (int c = 0; c < 4; c++) {
                const int kp0 = 8 * c + q;
                uint32_t v_h[2] = { vh_s[kp0 * VSTR + vcol], vh_s[(kp0 + 4) * VSTR + vcol] };
                uint32_t v_l[2] = { vl_s[kp0 * VSTR + vcol], vl_s[(kp0 + 4) * VSTR + vcol] };
                mma_bf16(o[n2], p_h[c], v_h);
                mma_bf16(o[n2], p_l[c], v_h);
                mma_bf16(o[n2], p_h[c], v_l);
            }
        }
    }

    // ---- epilogue: write AO fp16 hi/lo planes (consumed by fp16 GEMM) ----
    const float invA = 1.0f / l_A;
    const float invB = 1.0f / l_B;
    const size_t prow = (size_t)b * SEQ;
#pragma unroll
    for (int n2 = 0; n2 < 16; n2++) {
        const int pidx = h * 64 + 4 * n2 + q;
        uint32_t h0, l0, h1, l1;
        split2_f16(make_float2(o[n2][0] * invA, o[n2][1] * invA), h0, l0);
        split2_f16(make_float2(o[n2][2] * invB, o[n2][3] * invB), h1, l1);
        AOh[(prow + rowA) * KW + pidx] = h0;
        AOl[(prow + rowA) * KW + pidx] = l0;
        AOh[(prow + rowB) * KW + pidx] = h1;
        AOl[(prow + rowB) * KW + pidx] = l1;
    }
}

// ---------------------------------------------------------------------------
// Launcher
// ---------------------------------------------------------------------------
extern "C" void kernel_launch(void* const* d_in, const int* in_sizes, int n_in,
                              void* d_out, int out_size)
{
    const float* x  = (const float*)d_in[0];
    const float* Wq = (const float*)d_in[1];
    const float* Wk = (const float*)d_in[2];
    const float* Wv = (const float*)d_in[3];
    const float* Wo = (const float*)d_in[4];
    float* out = (float*)d_out;

    void *pV, *pXh, *pXl, *pWh, *pWl, *pQh, *pQl, *pKh, *pKl;
    cudaGetSymbolAddress(&pV,  g_V);
    cudaGetSymbolAddress(&pXh, g_Xhi);
    cudaGetSymbolAddress(&pXl, g_Xlo);
    cudaGetSymbolAddress(&pWh, g_Whi);
    cudaGetSymbolAddress(&pWl, g_Wlo);
    cudaGetSymbolAddress(&pQh, g_QPh);
    cudaGetSymbolAddress(&pQl, g_QPl);
    cudaGetSymbolAddress(&pKh, g_KPh);
    cudaGetSymbolAddress(&pKl, g_KPl);

    uint32_t* Xh = (uint32_t*)pXh; uint32_t* Xl = (uint32_t*)pXl;
    uint32_t* Wh = (uint32_t*)pWh; uint32_t* Wl = (uint32_t*)pWl;

    cudaFuncSetAttribute(gemm_qkv,
                         cudaFuncAttributeMaxDynamicSharedMemorySize, GEMM_SMEM_BYTES);
    cudaFuncSetAttribute(gemm_pre,
                         cudaFuncAttributeMaxDynamicSharedMemorySize, GEMM_SMEM_BYTES);
    cudaFuncSetAttribute(attn_mma,
                         cudaFuncAttributeMaxDynamicSharedMemorySize, AT_SMEM_BYTES);

    const int n2x = MROWS * D_MODEL / 2;      // 8388608
    const int n2w = D_MODEL * D_MODEL / 2;    // 2097152

    // fp16 splits: x and fused weights (W lo planes written but unused)
    split_f16_kernel<<<n2x / 256, 256>>>(x, Xh, Xl, n2x);
    split_f16_kernel<<<n2w / 256, 256>>>(Wq, Wh,            Wl,            n2w);
    split_f16_kernel<<<n2w / 256, 256>>>(Wk, Wh + (size_t)n2w,     Wl + (size_t)n2w,     n2w);
    split_f16_kernel<<<n2w / 256, 256>>>(Wv, Wh + (size_t)2 * n2w, Wl + (size_t)2 * n2w, n2w);

    // fused QKV projection: [8192, 6144]
    const dim3 qkv_grid(3 * D_MODEL / GBN, MROWS / GBM);  // (24, 64)
    gemm_qkv<<<qkv_grid, 256, GEMM_SMEM_BYTES>>>(
        Xh, Xl, Wh,
        (uint32_t*)pQh, (uint32_t*)pQl, (uint32_t*)pKh, (uint32_t*)pKl,
        (float*)pV);

    // attention (writes fp16 AO planes into Xh/Xl)
    const dim3 attn_grid(SEQ / 64, BATCH * NHEADS);       // (32, 64)
    attn_mma<<<attn_grid, AT_THREADS, AT_SMEM_BYTES>>>(
        (const uint32_t*)pQh, (const uint32_t*)pQl,
        (const uint32_t*)pKh, (const uint32_t*)pKl,
        (const float*)pV, Xh, Xl);

    // Wo fp16 planes (reuse slice 0)
    split_f16_kernel<<<n2w / 256, 256>>>(Wo, Wh, Wl, n2w);

    // final projection: out = AO @ Wo^T
    const dim3 ogrid(D_MODEL / GBN, MROWS / GBM);         // (8, 64)
    gemm_pre<<<ogrid, 256, GEMM_SMEM_BYTES>>>(Xh, Xl, Wh, out);
}